// round 10
// baseline (speedup 1.0000x reference)
#include <cuda_runtime.h>
#include <cuda_bf16.h>
#include <cuda_fp8.h>
#include <cstdint>
#include <math.h>

#define NROWS 16384
#define DIM   1024
#define BM 128
#define BN 256
#define BKB 256                // BYTES per k-slice per row (fp8: k256 elems)
#define NK (DIM / BKB)         // 4 k-slices (1024 fp8 bytes per row)
#define STAGES 2
#define A_STAGE 32768          // 128 rows * 256 B
#define B_STAGE 65536          // 256 rows * 256 B
#define SMEM_DYN (STAGES * (A_STAGE + B_STAGE))   // 192 KB
#define NCOLB (NROWS / BN)     // 64
#define NTILES (NCOLB * NCOLB + NCOLB)            // 4160
#define GRID_P 152             // persistent: one CTA per SM

// Scratch (device globals: no allocations allowed)
__device__ uint8_t            g_xq[(size_t)NROWS * DIM];   // 16 MB e4m3-quantized normalized rows
__device__ unsigned long long g_best[NROWS];               // packed (ordered_key<<32 | col)
__device__ float              g_partial[4096];

__device__ __forceinline__ unsigned int f2ord(float f) {
    unsigned int u = __float_as_uint(f);
    return (u & 0x80000000u) ? ~u : (u | 0x80000000u);
}
__device__ __forceinline__ uint32_t smem_u32(const void* p) {
    uint32_t a;
    asm("{ .reg .u64 t; cvta.to.shared.u64 t, %1; cvt.u32.u64 %0, t; }" : "=r"(a) : "l"(p));
    return a;
}
__device__ __forceinline__ void cp16(uint32_t dst, const void* src) {
    asm volatile("cp.async.cg.shared.global [%0], [%1], 16;" :: "r"(dst), "l"(src));
}
#define CP_COMMIT() asm volatile("cp.async.commit_group;" ::: "memory")
#define CP_WAIT0()  asm volatile("cp.async.wait_group 0;" ::: "memory")

#define LDSM_X4(r0, r1, r2, r3, addr) \
    asm volatile("ldmatrix.sync.aligned.m8n8.x4.shared.b16 {%0,%1,%2,%3}, [%4];" \
        : "=r"(r0), "=r"(r1), "=r"(r2), "=r"(r3) : "r"(addr))

// fp8 e4m3 MMA: m16n8k32, fragment byte-layout identical to bf16 m16n8k16
__device__ __forceinline__ void mma_fp8(float* c, const uint32_t* a, const uint32_t* b) {
    asm volatile(
        "mma.sync.aligned.m16n8k32.row.col.f32.e4m3.e4m3.f32 "
        "{%0,%1,%2,%3}, {%4,%5,%6,%7}, {%8,%9}, {%0,%1,%2,%3};\n"
        : "+f"(c[0]), "+f"(c[1]), "+f"(c[2]), "+f"(c[3])
        : "r"(a[0]), "r"(a[1]), "r"(a[2]), "r"(a[3]), "r"(b[0]), "r"(b[1]));
}

__device__ __forceinline__ void decode_tile(int id, int& rowBase, int& colBase) {
    int bi = (int)((sqrtf(4.0f * (float)id + 1.0f) - 1.0f) * 0.5f);
    while (bi * bi + bi > id) --bi;
    while ((bi + 1) * (bi + 1) + (bi + 1) <= id) ++bi;
    const int bj = id - bi * bi - bi;            // 0 .. 2*bi+1
    rowBase = bj * BM;
    colBase = bi * BN;
}

// ---------------- Kernel 1: normalize -> e4m3 (scale 16), init best ----------------
__global__ void prep_kernel(const float* __restrict__ x) {
    const int row = blockIdx.x;
    const int t = threadIdx.x;              // 256 threads, 4 elems each
    const float4 a = ((const float4*)(x + (size_t)row * DIM))[t];
    float s = a.x * a.x + a.y * a.y + a.z * a.z + a.w * a.w;
    #pragma unroll
    for (int off = 16; off > 0; off >>= 1) s += __shfl_xor_sync(0xffffffffu, s, off);
    __shared__ float red[8];
    __shared__ float s_total;
    const int wid = t >> 5, lane = t & 31;
    if (lane == 0) red[wid] = s;
    __syncthreads();
    if (t == 0) {
        float tt = 0.f;
        #pragma unroll
        for (int i = 0; i < 8; i++) tt += red[i];
        s_total = tt;
        g_best[row] = 0ull;   // re-init every launch (graph replay safe)
    }
    __syncthreads();
    const float scale = 16.0f / fmaxf(sqrtf(s_total), 1e-8f);   // power-of-2 scale: argmax invariant
    __nv_fp8x2_storage_t lo = __nv_cvt_float2_to_fp8x2(
        make_float2(a.x * scale, a.y * scale), __NV_SATFINITE, __NV_E4M3);
    __nv_fp8x2_storage_t hi = __nv_cvt_float2_to_fp8x2(
        make_float2(a.z * scale, a.w * scale), __NV_SATFINITE, __NV_E4M3);
    ((uint32_t*)(g_xq + (size_t)row * DIM))[t] = (uint32_t)lo | ((uint32_t)hi << 16);
}

// ---------------- Kernel 2: persistent fused triangular fp8 GEMM + dual argmax ----------------
extern __shared__ __align__(128) char smem_dyn[];

__global__ __launch_bounds__(256) void nn_gemm_kernel() {
    __shared__ unsigned long long sred[BM];
    __shared__ unsigned long long scol[BN];

    const int tid = threadIdx.x;
    const int lane = tid & 31;
    const int warpId = tid >> 5;

    const uint32_t smA = smem_u32(smem_dyn);
    const uint32_t smB = smA + STAGES * A_STAGE;

    // ---- per-thread ldmatrix address components (byte-identical to bf16 k16) ----
    const int wM = warpId & 1, wN = warpId >> 1;      // 2 x 4 warps
    const int wrb = wM * 64, wcb = wN * 64;           // warp tile 64x64
    const int arow = wrb + (lane & 7) + ((lane >> 3) & 1) * 8;
    const int achk = lane >> 4;                       // 0/1 (16B chunk within 32B k-chunk)
    const int asw  = arow & 7;
    const int brow = wcb + (lane & 7) + ((lane >> 4) & 1) * 8;
    const int bchk = (lane >> 3) & 1;
    const int bsw  = brow & 7;

    // cp.async mapping: A 2048 16B-chunks/stage (8/thread), B 4096 (16/thread)
    const int cpr  = tid >> 4;           // base row (stride 16 rows)
    const int cpc  = tid & 15;           // chunk col 0..15 (16B units within 256B row-slice)

    int tId = blockIdx.x;
    if (tId >= NTILES) return;
    int rowBase, colBase;
    decode_tile(tId, rowBase, colBase);

    // ---- first tile prologue: stage 0 -> slot 0 ----
    {
        const uint8_t* gA = g_xq + (size_t)rowBase * DIM;
        const uint8_t* gB = g_xq + (size_t)colBase * DIM;
        #pragma unroll
        for (int i = 0; i < 8; i++) {
            const int r = cpr + i * 16;
            cp16(smA + r * 256 + ((cpc ^ (r & 7)) << 4), gA + (size_t)r * DIM + cpc * 16);
        }
        #pragma unroll
        for (int i = 0; i < 16; i++) {
            const int r = cpr + i * 16;
            cp16(smB + r * 256 + ((cpc ^ (r & 7)) << 4), gB + (size_t)r * DIM + cpc * 16);
        }
        CP_COMMIT();
    }

    while (true) {
        const bool isDiag = (rowBase >= colBase);
        const int nextId = tId + GRID_P;
        const bool hasNext = (nextId < NTILES);
        int nRowBase = 0, nColBase = 0;
        if (hasNext) decode_tile(nextId, nRowBase, nColBase);

        const uint8_t* gA = g_xq + (size_t)rowBase * DIM;
        const uint8_t* gB = g_xq + (size_t)colBase * DIM;

        if (tid < BM) sred[tid] = 0ull;
        scol[tid] = 0ull;

        float acc[4][8][4];
        #pragma unroll
        for (int i = 0; i < 4; i++)
            #pragma unroll
            for (int j = 0; j < 8; j++)
                #pragma unroll
                for (int k = 0; k < 4; k++) acc[i][j][k] = 0.f;

        for (int kt = 0; kt < NK; kt++) {
            CP_WAIT0();
            __syncthreads();

            const int cur = kt & 1;
            const uint32_t Ab = smA + cur * A_STAGE;
            const uint32_t Bb = smB + cur * B_STAGE;

            // ---- peel chunk 0 fragment loads ----
            uint32_t ra[4][4], rb[8][2];
            #pragma unroll
            for (int mt = 0; mt < 4; mt++) {
                const uint32_t a = Ab + (arow + mt * 16) * 256 + ((achk ^ asw) << 4);
                LDSM_X4(ra[mt][0], ra[mt][1], ra[mt][2], ra[mt][3], a);
            }
            #pragma unroll
            for (int p = 0; p < 4; p++) {
                const uint32_t b = Bb + (brow + p * 16) * 256 + ((bchk ^ bsw) << 4);
                LDSM_X4(rb[2 * p][0], rb[2 * p][1], rb[2 * p + 1][0], rb[2 * p + 1][1], b);
            }

            // ---- issue loads into the other slot ----
            const int nxt = cur ^ 1;
            if (kt + 1 < NK) {
                const int ko = (kt + 1) * BKB;
                #pragma unroll
                for (int i = 0; i < 8; i++) {
                    const int r = cpr + i * 16;
                    cp16(smA + nxt * A_STAGE + r * 256 + ((cpc ^ (r & 7)) << 4),
                         gA + (size_t)r * DIM + ko + cpc * 16);
                }
                #pragma unroll
                for (int i = 0; i < 16; i++) {
                    const int r = cpr + i * 16;
                    cp16(smB + nxt * B_STAGE + r * 256 + ((cpc ^ (r & 7)) << 4),
                         gB + (size_t)r * DIM + ko + cpc * 16);
                }
            } else if (hasNext) {
                // cross-tile prefetch: next tile's stage 0 -> slot 0 (NK even)
                const uint8_t* nA = g_xq + (size_t)nRowBase * DIM;
                const uint8_t* nB = g_xq + (size_t)nColBase * DIM;
                #pragma unroll
                for (int i = 0; i < 8; i++) {
                    const int r = cpr + i * 16;
                    cp16(smA + nxt * A_STAGE + r * 256 + ((cpc ^ (r & 7)) << 4),
                         nA + (size_t)r * DIM + cpc * 16);
                }
                #pragma unroll
                for (int i = 0; i < 16; i++) {
                    const int r = cpr + i * 16;
                    cp16(smB + nxt * B_STAGE + r * 256 + ((cpc ^ (r & 7)) << 4),
                         nB + (size_t)r * DIM + cpc * 16);
                }
            }
            CP_COMMIT();

            // ---- mma chunk 0 (k32) ----
            #pragma unroll
            for (int mt = 0; mt < 4; mt++)
                #pragma unroll
                for (int nt = 0; nt < 8; nt++)
                    mma_fp8(acc[mt][nt], ra[mt], rb[nt]);

            // ---- chunks 1..7 (each 32B = k32) ----
            #pragma unroll
            for (int kk = 1; kk < 8; kk++) {
                #pragma unroll
                for (int mt = 0; mt < 4; mt++) {
                    const uint32_t a = Ab + (arow + mt * 16) * 256 + (((kk * 2 + achk) ^ asw) << 4);
                    LDSM_X4(ra[mt][0], ra[mt][1], ra[mt][2], ra[mt][3], a);
                }
                #pragma unroll
                for (int p = 0; p < 4; p++) {
                    const uint32_t b = Bb + (brow + p * 16) * 256 + (((kk * 2 + bchk) ^ bsw) << 4);
                    LDSM_X4(rb[2 * p][0], rb[2 * p][1], rb[2 * p + 1][0], rb[2 * p + 1][1], b);
                }
                #pragma unroll
                for (int mt = 0; mt < 4; mt++)
                    #pragma unroll
                    for (int nt = 0; nt < 8; nt++)
                        mma_fp8(acc[mt][nt], ra[mt], rb[nt]);
            }
        }

        const int g = lane >> 2, t4 = lane & 3;

        // ---- epilogue A: per-row argmax over this tile's 256 columns, diag masked ----
        #pragma unroll
        for (int mt = 0; mt < 4; mt++) {
            const int r0 = rowBase + wrb + mt * 16 + g;
            const int r1 = r0 + 8;
            float m0 = -1e30f, m1 = -1e30f;
            int j0 = 0, j1 = 0;
            #pragma unroll
            for (int nt = 0; nt < 8; nt++) {
                const int c = colBase + wcb + nt * 8 + 2 * t4;
                float v;
                v = acc[mt][nt][0]; if (c     != r0 && v > m0) { m0 = v; j0 = c;     }
                v = acc[mt][nt][1]; if (c + 1 != r0 && v > m0) { m0 = v; j0 = c + 1; }
                v = acc[mt][nt][2]; if (c     != r1 && v > m1) { m1 = v; j1 = c;     }
                v = acc[mt][nt][3]; if (c + 1 != r1 && v > m1) { m1 = v; j1 = c + 1; }
            }
            unsigned long long p0 = ((unsigned long long)f2ord(m0) << 32) | (unsigned)j0;
            unsigned long long p1 = ((unsigned long long)f2ord(m1) << 32) | (unsigned)j1;
            #pragma unroll
            for (int off = 1; off < 4; off <<= 1) {
                unsigned long long q0 = __shfl_xor_sync(0xffffffffu, p0, off);
                unsigned long long q1 = __shfl_xor_sync(0xffffffffu, p1, off);
                if (q0 > p0) p0 = q0;
                if (q1 > p1) p1 = q1;
            }
            if (t4 == 0) {
                atomicMax(&sred[wrb + mt * 16 + g], p0);
                atomicMax(&sred[wrb + mt * 16 + g + 8], p1);
            }
        }

        // ---- epilogue B: per-column argmax (symmetry), off-diag tiles only ----
        if (!isDiag) {
            #pragma unroll
            for (int nt = 0; nt < 8; nt++) {
                const int cl = wcb + nt * 8 + 2 * t4;
                float ce = -1e30f, co = -1e30f;
                int re = 0, ro = 0;
                #pragma unroll
                for (int mt = 0; mt < 4; mt++) {
                    const int r0 = rowBase + wrb + mt * 16 + g;
                    const int r1 = r0 + 8;
                    float v;
                    v = acc[mt][nt][0]; if (v > ce) { ce = v; re = r0; }
                    v = acc[mt][nt][2]; if (v > ce) { ce = v; re = r1; }
                    v = acc[mt][nt][1]; if (v > co) { co = v; ro = r0; }
                    v = acc[mt][nt][3]; if (v > co) { co = v; ro = r1; }
                }
                unsigned long long pe = ((unsigned long long)f2ord(ce) << 32) | (unsigned)re;
                unsigned long long po = ((unsigned long long)f2ord(co) << 32) | (unsigned)ro;
                #pragma unroll
                for (int off = 4; off < 32; off <<= 1) {
                    unsigned long long qe = __shfl_xor_sync(0xffffffffu, pe, off);
                    unsigned long long qo = __shfl_xor_sync(0xffffffffu, po, off);
                    if (qe > pe) pe = qe;
                    if (qo > po) po = qo;
                }
                if (g == 0) {
                    atomicMax(&scol[cl], pe);
                    atomicMax(&scol[cl + 1], po);
                }
            }
        }

        __syncthreads();
        if (tid < BM) atomicMax(&g_best[rowBase + tid], sred[tid]);
        if (!isDiag) atomicMax(&g_best[colBase + tid], scol[tid]);
        __syncthreads();   // protect sred/scol from next tile's re-zeroing

        if (!hasNext) break;
        tId = nextId;
        rowBase = nRowBase;
        colBase = nColBase;
    }
}

// ---------------- Kernel 3: distances + per-warp partial of -log(d) ----------------
__global__ void loss_kernel(const float* __restrict__ x) {
    const int gw = (blockIdx.x * blockDim.x + threadIdx.x) >> 5;  // 4096 warps
    const int lane = threadIdx.x & 31;
    float accum = 0.f;
    for (int row = gw; row < NROWS; row += 4096) {
        const int j = (int)(g_best[row] & 0xffffffffu);
        const float4* a = (const float4*)(x + (size_t)row * DIM);
        const float4* b = (const float4*)(x + (size_t)j * DIM);
        float s = 0.f;
        #pragma unroll 4
        for (int i = lane; i < DIM / 4; i += 32) {
            float4 va = a[i], vb = b[i];
            float d0 = va.x - vb.x + 1e-6f;
            float d1 = va.y - vb.y + 1e-6f;
            float d2 = va.z - vb.z + 1e-6f;
            float d3 = va.w - vb.w + 1e-6f;
            s += d0 * d0 + d1 * d1 + d2 * d2 + d3 * d3;
        }
        #pragma unroll
        for (int off = 16; off > 0; off >>= 1) s += __shfl_xor_sync(0xffffffffu, s, off);
        if (lane == 0) accum += -0.5f * logf(s);   // -log(sqrt(s))
    }
    if (lane == 0) g_partial[gw] = accum;
}

// ---------------- Kernel 4: deterministic final reduction ----------------
__global__ void reduce_kernel(float* __restrict__ out) {
    __shared__ float red[256];
    const int t = threadIdx.x;
    float s = 0.f;
    for (int i = t; i < 4096; i += 256) s += g_partial[i];
    red[t] = s;
    __syncthreads();
    for (int o = 128; o > 0; o >>= 1) {
        if (t < o) red[t] += red[t + o];
        __syncthreads();
    }
    if (t == 0) out[0] = red[0] * (1.0f / NROWS);
}

extern "C" void kernel_launch(void* const* d_in, const int* in_sizes, int n_in,
                              void* d_out, int out_size) {
    (void)in_sizes; (void)n_in; (void)out_size;
    const float* x = (const float*)d_in[0];
    float* out = (float*)d_out;

    cudaFuncSetAttribute(nn_gemm_kernel, cudaFuncAttributeMaxDynamicSharedMemorySize, SMEM_DYN);

    prep_kernel<<<NROWS, 256>>>(x);
    nn_gemm_kernel<<<GRID_P, 256, SMEM_DYN>>>();
    loss_kernel<<<512, 256>>>(x);
    reduce_kernel<<<1, 256>>>(out);
}

// round 11
// speedup vs baseline: 1.1258x; 1.1258x over previous
#include <cuda_runtime.h>
#include <cuda_bf16.h>
#include <cstdint>
#include <math.h>

#define NROWS 16384
#define DIM   1024
#define BM 128
#define BN 256
#define BK 128                 // bf16 elems per k-slice = 256 B per row
#define NK (DIM / BK)          // 8
#define STAGES 2
#define A_STAGE 32768          // 128 rows * 256 B
#define B_STAGE 65536          // 256 rows * 256 B
#define SMEM_DYN (STAGES * (A_STAGE + B_STAGE))   // 192 KB
#define NCOLB (NROWS / BN)     // 64
#define NTILES (NCOLB * NCOLB + NCOLB)            // 4160
#define GRID_P 152             // persistent: one CTA per SM (GB300 = 152 SMs)

// Scratch (device globals: no allocations allowed)
__device__ __nv_bfloat16      g_xn[(size_t)NROWS * DIM];   // 32 MB normalized bf16
__device__ unsigned long long g_best[NROWS];               // packed (ordered_key<<32 | col)
__device__ float              g_partial[4096];

__device__ __forceinline__ unsigned int f2ord(float f) {
    unsigned int u = __float_as_uint(f);
    return (u & 0x80000000u) ? ~u : (u | 0x80000000u);
}
__device__ __forceinline__ uint32_t smem_u32(const void* p) {
    uint32_t a;
    asm("{ .reg .u64 t; cvta.to.shared.u64 t, %1; cvt.u32.u64 %0, t; }" : "=r"(a) : "l"(p));
    return a;
}
__device__ __forceinline__ void cp16(uint32_t dst, const void* src) {
    asm volatile("cp.async.cg.shared.global [%0], [%1], 16;" :: "r"(dst), "l"(src));
}
#define CP_COMMIT() asm volatile("cp.async.commit_group;" ::: "memory")
#define CP_WAIT0()  asm volatile("cp.async.wait_group 0;" ::: "memory")

#define LDSM_X4(r0, r1, r2, r3, addr) \
    asm volatile("ldmatrix.sync.aligned.m8n8.x4.shared.b16 {%0,%1,%2,%3}, [%4];" \
        : "=r"(r0), "=r"(r1), "=r"(r2), "=r"(r3) : "r"(addr))

__device__ __forceinline__ void mma16816(float* c, const uint32_t* a, const uint32_t* b) {
    asm volatile(
        "mma.sync.aligned.m16n8k16.row.col.f32.bf16.bf16.f32 "
        "{%0,%1,%2,%3}, {%4,%5,%6,%7}, {%8,%9}, {%0,%1,%2,%3};\n"
        : "+f"(c[0]), "+f"(c[1]), "+f"(c[2]), "+f"(c[3])
        : "r"(a[0]), "r"(a[1]), "r"(a[2]), "r"(a[3]), "r"(b[0]), "r"(b[1]));
}

__device__ __forceinline__ void decode_tile(int id, int& rowBase, int& colBase) {
    int bi = (int)((sqrtf(4.0f * (float)id + 1.0f) - 1.0f) * 0.5f);
    while (bi * bi + bi > id) --bi;
    while ((bi + 1) * (bi + 1) + (bi + 1) <= id) ++bi;
    const int bj = id - bi * bi - bi;            // 0 .. 2*bi+1
    rowBase = bj * BM;
    colBase = bi * BN;
}

// ---------------- Kernel 1: normalize -> bf16, init best ----------------
__global__ void prep_kernel(const float* __restrict__ x) {
    const int row = blockIdx.x;
    const int t = threadIdx.x;              // 256 threads
    const float4 a = ((const float4*)(x + (size_t)row * DIM))[t];
    float s = a.x * a.x + a.y * a.y + a.z * a.z + a.w * a.w;
    #pragma unroll
    for (int off = 16; off > 0; off >>= 1) s += __shfl_xor_sync(0xffffffffu, s, off);
    __shared__ float red[8];
    __shared__ float s_total;
    const int wid = t >> 5, lane = t & 31;
    if (lane == 0) red[wid] = s;
    __syncthreads();
    if (t == 0) {
        float tt = 0.f;
        #pragma unroll
        for (int i = 0; i < 8; i++) tt += red[i];
        s_total = tt;
        g_best[row] = 0ull;   // re-init every launch (graph replay safe)
    }
    __syncthreads();
    const float scale = 1.0f / fmaxf(sqrtf(s_total), 1e-8f);
    __nv_bfloat162* o2 = (__nv_bfloat162*)(g_xn + (size_t)row * DIM);
    o2[2 * t]     = __floats2bfloat162_rn(a.x * scale, a.y * scale);
    o2[2 * t + 1] = __floats2bfloat162_rn(a.z * scale, a.w * scale);
}

// ---------------- Kernel 2: persistent fused triangular GEMM + dual argmax ----------------
extern __shared__ __align__(128) char smem_dyn[];

__global__ __launch_bounds__(256) void nn_gemm_kernel() {
    __shared__ unsigned long long sred[BM];
    __shared__ unsigned long long scol[BN];

    const int tid = threadIdx.x;
    const int lane = tid & 31;
    const int warpId = tid >> 5;

    const uint32_t smA = smem_u32(smem_dyn);
    const uint32_t smB = smA + STAGES * A_STAGE;

    // ---- per-thread ldmatrix address components ----
    const int wM = warpId & 1, wN = warpId >> 1;      // 2 x 4 warps
    const int wrb = wM * 64, wcb = wN * 64;           // warp tile 64x64
    const int arow = wrb + (lane & 7) + ((lane >> 3) & 1) * 8;
    const int achk = lane >> 4;                       // 0/1 (16B chunk within k16)
    const int asw  = arow & 7;
    const int brow = wcb + (lane & 7) + ((lane >> 4) & 1) * 8;
    const int bchk = (lane >> 3) & 1;
    const int bsw  = brow & 7;

    // cp.async mapping: A 2048 16B-chunks/stage (8/thread), B 4096 (16/thread)
    const int cpr  = tid >> 4;           // base row (stride 16 rows)
    const int cpc  = tid & 15;           // chunk col 0..15

    int tId = blockIdx.x;
    if (tId >= NTILES) return;
    int rowBase, colBase;
    decode_tile(tId, rowBase, colBase);

    // ---- first tile prologue: stage 0 -> slot 0 ----
    {
        const __nv_bfloat16* gA = g_xn + (size_t)rowBase * DIM;
        const __nv_bfloat16* gB = g_xn + (size_t)colBase * DIM;
        #pragma unroll
        for (int i = 0; i < 8; i++) {
            const int r = cpr + i * 16;
            cp16(smA + r * 256 + ((cpc ^ (r & 7)) << 4), gA + (size_t)r * DIM + cpc * 8);
        }
        #pragma unroll
        for (int i = 0; i < 16; i++) {
            const int r = cpr + i * 16;
            cp16(smB + r * 256 + ((cpc ^ (r & 7)) << 4), gB + (size_t)r * DIM + cpc * 8);
        }
        CP_COMMIT();
    }

    while (true) {
        const bool isDiag = (rowBase >= colBase);
        const int nextId = tId + GRID_P;
        const bool hasNext = (nextId < NTILES);
        int nRowBase = 0, nColBase = 0;
        if (hasNext) decode_tile(nextId, nRowBase, nColBase);

        const __nv_bfloat16* gA = g_xn + (size_t)rowBase * DIM;
        const __nv_bfloat16* gB = g_xn + (size_t)colBase * DIM;

        if (tid < BM) sred[tid] = 0ull;
        scol[tid] = 0ull;

        float acc[4][8][4];
        #pragma unroll
        for (int i = 0; i < 4; i++)
            #pragma unroll
            for (int j = 0; j < 8; j++)
                #pragma unroll
                for (int k = 0; k < 4; k++) acc[i][j][k] = 0.f;

        for (int kt = 0; kt < NK; kt++) {
            CP_WAIT0();
            __syncthreads();

            const int cur = kt & 1;
            const uint32_t Ab = smA + cur * A_STAGE;
            const uint32_t Bb = smB + cur * B_STAGE;

            // ---- chunk 0: ldsm then mma IMMEDIATELY (in-order issue: get the
            //      tensor pipe busy before the cp.async issue burst) ----
            uint32_t ra[4][4], rb[8][2];
            #pragma unroll
            for (int mt = 0; mt < 4; mt++) {
                const uint32_t a = Ab + (arow + mt * 16) * 256 + ((achk ^ asw) << 4);
                LDSM_X4(ra[mt][0], ra[mt][1], ra[mt][2], ra[mt][3], a);
            }
            #pragma unroll
            for (int p = 0; p < 4; p++) {
                const uint32_t b = Bb + (brow + p * 16) * 256 + ((bchk ^ bsw) << 4);
                LDSM_X4(rb[2 * p][0], rb[2 * p][1], rb[2 * p + 1][0], rb[2 * p + 1][1], b);
            }
            #pragma unroll
            for (int mt = 0; mt < 4; mt++)
                #pragma unroll
                for (int nt = 0; nt < 8; nt++)
                    mma16816(acc[mt][nt], ra[mt], rb[nt]);

            // ---- cp.async burst now issues under chunk-0's tensor drain ----
            const int nxt = cur ^ 1;
            if (kt + 1 < NK) {
                const int ko = (kt + 1) * BK;
                #pragma unroll
                for (int i = 0; i < 8; i++) {
                    const int r = cpr + i * 16;
                    cp16(smA + nxt * A_STAGE + r * 256 + ((cpc ^ (r & 7)) << 4),
                         gA + (size_t)r * DIM + ko + cpc * 8);
                }
                #pragma unroll
                for (int i = 0; i < 16; i++) {
                    const int r = cpr + i * 16;
                    cp16(smB + nxt * B_STAGE + r * 256 + ((cpc ^ (r & 7)) << 4),
                         gB + (size_t)r * DIM + ko + cpc * 8);
                }
            } else if (hasNext) {
                // cross-tile prefetch: next tile's stage 0 -> slot 0 (NK even)
                const __nv_bfloat16* nA = g_xn + (size_t)nRowBase * DIM;
                const __nv_bfloat16* nB = g_xn + (size_t)nColBase * DIM;
                #pragma unroll
                for (int i = 0; i < 8; i++) {
                    const int r = cpr + i * 16;
                    cp16(smA + nxt * A_STAGE + r * 256 + ((cpc ^ (r & 7)) << 4),
                         nA + (size_t)r * DIM + cpc * 8);
                }
                #pragma unroll
                for (int i = 0; i < 16; i++) {
                    const int r = cpr + i * 16;
                    cp16(smB + nxt * B_STAGE + r * 256 + ((cpc ^ (r & 7)) << 4),
                         nB + (size_t)r * DIM + cpc * 8);
                }
            }
            CP_COMMIT();

            // ---- chunks 1..7 ----
            #pragma unroll
            for (int kk = 1; kk < 8; kk++) {
                #pragma unroll
                for (int mt = 0; mt < 4; mt++) {
                    const uint32_t a = Ab + (arow + mt * 16) * 256 + (((kk * 2 + achk) ^ asw) << 4);
                    LDSM_X4(ra[mt][0], ra[mt][1], ra[mt][2], ra[mt][3], a);
                }
                #pragma unroll
                for (int p = 0; p < 4; p++) {
                    const uint32_t b = Bb + (brow + p * 16) * 256 + (((kk * 2 + bchk) ^ bsw) << 4);
                    LDSM_X4(rb[2 * p][0], rb[2 * p][1], rb[2 * p + 1][0], rb[2 * p + 1][1], b);
                }
                #pragma unroll
                for (int mt = 0; mt < 4; mt++)
                    #pragma unroll
                    for (int nt = 0; nt < 8; nt++)
                        mma16816(acc[mt][nt], ra[mt], rb[nt]);
            }
        }

        const int g = lane >> 2, t4 = lane & 3;

        // ---- epilogue A: per-row argmax over this tile's 256 columns, diag masked ----
        #pragma unroll
        for (int mt = 0; mt < 4; mt++) {
            const int r0 = rowBase + wrb + mt * 16 + g;
            const int r1 = r0 + 8;
            float m0 = -10.f, m1 = -10.f;
            int j0 = 0, j1 = 0;
            #pragma unroll
            for (int nt = 0; nt < 8; nt++) {
                const int c = colBase + wcb + nt * 8 + 2 * t4;
                float v;
                v = acc[mt][nt][0]; if (c     != r0 && v > m0) { m0 = v; j0 = c;     }
                v = acc[mt][nt][1]; if (c + 1 != r0 && v > m0) { m0 = v; j0 = c + 1; }
                v = acc[mt][nt][2]; if (c     != r1 && v > m1) { m1 = v; j1 = c;     }
                v = acc[mt][nt][3]; if (c + 1 != r1 && v > m1) { m1 = v; j1 = c + 1; }
            }
            unsigned long long p0 = ((unsigned long long)f2ord(m0) << 32) | (unsigned)j0;
            unsigned long long p1 = ((unsigned long long)f2ord(m1) << 32) | (unsigned)j1;
            #pragma unroll
            for (int off = 1; off < 4; off <<= 1) {
                unsigned long long q0 = __shfl_xor_sync(0xffffffffu, p0, off);
                unsigned long long q1 = __shfl_xor_sync(0xffffffffu, p1, off);
                if (q0 > p0) p0 = q0;
                if (q1 > p1) p1 = q1;
            }
            if (t4 == 0) {
                atomicMax(&sred[wrb + mt * 16 + g], p0);
                atomicMax(&sred[wrb + mt * 16 + g + 8], p1);
            }
        }

        // ---- epilogue B: per-column argmax (symmetry), off-diag tiles only ----
        if (!isDiag) {
            #pragma unroll
            for (int nt = 0; nt < 8; nt++) {
                const int cl = wcb + nt * 8 + 2 * t4;
                float ce = -10.f, co = -10.f;
                int re = 0, ro = 0;
                #pragma unroll
                for (int mt = 0; mt < 4; mt++) {
                    const int r0 = rowBase + wrb + mt * 16 + g;
                    const int r1 = r0 + 8;
                    float v;
                    v = acc[mt][nt][0]; if (v > ce) { ce = v; re = r0; }
                    v = acc[mt][nt][2]; if (v > ce) { ce = v; re = r1; }
                    v = acc[mt][nt][1]; if (v > co) { co = v; ro = r0; }
                    v = acc[mt][nt][3]; if (v > co) { co = v; ro = r1; }
                }
                unsigned long long pe = ((unsigned long long)f2ord(ce) << 32) | (unsigned)re;
                unsigned long long po = ((unsigned long long)f2ord(co) << 32) | (unsigned)ro;
                #pragma unroll
                for (int off = 4; off < 32; off <<= 1) {
                    unsigned long long qe = __shfl_xor_sync(0xffffffffu, pe, off);
                    unsigned long long qo = __shfl_xor_sync(0xffffffffu, po, off);
                    if (qe > pe) pe = qe;
                    if (qo > po) po = qo;
                }
                if (g == 0) {
                    atomicMax(&scol[cl], pe);
                    atomicMax(&scol[cl + 1], po);
                }
            }
        }

        __syncthreads();
        if (tid < BM) atomicMax(&g_best[rowBase + tid], sred[tid]);
        if (!isDiag) atomicMax(&g_best[colBase + tid], scol[tid]);
        __syncthreads();   // protect sred/scol from next tile's re-zeroing

        if (!hasNext) break;
        tId = nextId;
        rowBase = nRowBase;
        colBase = nColBase;
    }
}

// ---------------- Kernel 3: distances + per-warp partial of -log(d) ----------------
__global__ void loss_kernel(const float* __restrict__ x) {
    const int gw = (blockIdx.x * blockDim.x + threadIdx.x) >> 5;  // 4096 warps
    const int lane = threadIdx.x & 31;
    float accum = 0.f;
    for (int row = gw; row < NROWS; row += 4096) {
        const int j = (int)(g_best[row] & 0xffffffffu);
        const float4* a = (const float4*)(x + (size_t)row * DIM);
        const float4* b = (const float4*)(x + (size_t)j * DIM);
        float s = 0.f;
        #pragma unroll 4
        for (int i = lane; i < DIM / 4; i += 32) {
            float4 va = a[i], vb = b[i];
            float d0 = va.x - vb.x + 1e-6f;
            float d1 = va.y - vb.y + 1e-6f;
            float d2 = va.z - vb.z + 1e-6f;
            float d3 = va.w - vb.w + 1e-6f;
            s += d0 * d0 + d1 * d1 + d2 * d2 + d3 * d3;
        }
        #pragma unroll
        for (int off = 16; off > 0; off >>= 1) s += __shfl_xor_sync(0xffffffffu, s, off);
        if (lane == 0) accum += -0.5f * logf(s);   // -log(sqrt(s))
    }
    if (lane == 0) g_partial[gw] = accum;
}

// ---------------- Kernel 4: deterministic final reduction ----------------
__global__ void reduce_kernel(float* __restrict__ out) {
    __shared__ float red[256];
    const int t = threadIdx.x;
    float s = 0.f;
    for (int i = t; i < 4096; i += 256) s += g_partial[i];
    red[t] = s;
    __syncthreads();
    for (int o = 128; o > 0; o >>= 1) {
        if (t < o) red[t] += red[t + o];
        __syncthreads();
    }
    if (t == 0) out[0] = red[0] * (1.0f / NROWS);
}

extern "C" void kernel_launch(void* const* d_in, const int* in_sizes, int n_in,
                              void* d_out, int out_size) {
    (void)in_sizes; (void)n_in; (void)out_size;
    const float* x = (const float*)d_in[0];
    float* out = (float*)d_out;

    cudaFuncSetAttribute(nn_gemm_kernel, cudaFuncAttributeMaxDynamicSharedMemorySize, SMEM_DYN);

    prep_kernel<<<NROWS, 256>>>(x);
    nn_gemm_kernel<<<GRID_P, 256, SMEM_DYN>>>();
    loss_kernel<<<512, 256>>>(x);
    reduce_kernel<<<1, 256>>>(out);
}

// round 13
// speedup vs baseline: 1.1578x; 1.0283x over previous
#include <cuda_runtime.h>
#include <cuda_bf16.h>
#include <cstdint>
#include <math.h>

#define NROWS 16384
#define DIM   1024
#define BM 128
#define BN 256
#define BK 128                 // bf16 elems per k-slice = 256 B per row
#define NK (DIM / BK)          // 8
#define STAGES 2
#define A_STAGE 32768          // 128 rows * 256 B
#define B_STAGE 65536          // 256 rows * 256 B
#define SMEM_DYN (STAGES * (A_STAGE + B_STAGE))   // 192 KB
#define NCOLB (NROWS / BN)     // 64
#define NTILES (NCOLB * NCOLB + NCOLB)            // 4160
#define GRID_P 152             // persistent: one CTA per SM (GB300 = 152 SMs)
#define LOSS_BLOCKS 512

// Scratch (device globals: no allocations allowed)
__device__ __nv_bfloat16      g_xn[(size_t)NROWS * DIM];   // 32 MB normalized bf16
__device__ unsigned long long g_best[NROWS];               // packed (ordered_key<<32 | col)
__device__ float              g_partial[4096];
__device__ int                g_count;

__device__ __forceinline__ unsigned int f2ord(float f) {
    unsigned int u = __float_as_uint(f);
    return (u & 0x80000000u) ? ~u : (u | 0x80000000u);
}
__device__ __forceinline__ uint32_t smem_u32(const void* p) {
    uint32_t a;
    asm("{ .reg .u64 t; cvta.to.shared.u64 t, %1; cvt.u32.u64 %0, t; }" : "=r"(a) : "l"(p));
    return a;
}
__device__ __forceinline__ void cp16(uint32_t dst, const void* src) {
    asm volatile("cp.async.cg.shared.global [%0], [%1], 16;" :: "r"(dst), "l"(src));
}
#define CP_COMMIT() asm volatile("cp.async.commit_group;" ::: "memory")
#define CP_WAIT0()  asm volatile("cp.async.wait_group 0;" ::: "memory")

#define LDSM_X4(r0, r1, r2, r3, addr) \
    asm volatile("ldmatrix.sync.aligned.m8n8.x4.shared.b16 {%0,%1,%2,%3}, [%4];" \
        : "=r"(r0), "=r"(r1), "=r"(r2), "=r"(r3) : "r"(addr))

__device__ __forceinline__ void mma16816(float* c, const uint32_t* a, const uint32_t* b) {
    asm volatile(
        "mma.sync.aligned.m16n8k16.row.col.f32.bf16.bf16.f32 "
        "{%0,%1,%2,%3}, {%4,%5,%6,%7}, {%8,%9}, {%0,%1,%2,%3};\n"
        : "+f"(c[0]), "+f"(c[1]), "+f"(c[2]), "+f"(c[3])
        : "r"(a[0]), "r"(a[1]), "r"(a[2]), "r"(a[3]), "r"(b[0]), "r"(b[1]));
}

__device__ __forceinline__ void decode_tile(int id, int& rowBase, int& colBase) {
    int bi = (int)((sqrtf(4.0f * (float)id + 1.0f) - 1.0f) * 0.5f);
    while (bi * bi + bi > id) --bi;
    while ((bi + 1) * (bi + 1) + (bi + 1) <= id) ++bi;
    const int bj = id - bi * bi - bi;            // 0 .. 2*bi+1
    rowBase = bj * BM;
    colBase = bi * BN;
}

// ---------------- Kernel 1: normalize -> bf16, init best + counter ----------------
__global__ void prep_kernel(const float* __restrict__ x) {
    const int row = blockIdx.x;
    const int t = threadIdx.x;              // 256 threads
    const float4 a = ((const float4*)(x + (size_t)row * DIM))[t];
    float s = a.x * a.x + a.y * a.y + a.z * a.z + a.w * a.w;
    #pragma unroll
    for (int off = 16; off > 0; off >>= 1) s += __shfl_xor_sync(0xffffffffu, s, off);
    __shared__ float red[8];
    __shared__ float s_total;
    const int wid = t >> 5, lane = t & 31;
    if (lane == 0) red[wid] = s;
    __syncthreads();
    if (t == 0) {
        float tt = 0.f;
        #pragma unroll
        for (int i = 0; i < 8; i++) tt += red[i];
        s_total = tt;
        g_best[row] = 0ull;   // re-init every launch (graph replay safe)
        if (row == 0) g_count = 0;
    }
    __syncthreads();
    const float scale = 1.0f / fmaxf(sqrtf(s_total), 1e-8f);
    __nv_bfloat162* o2 = (__nv_bfloat162*)(g_xn + (size_t)row * DIM);
    o2[2 * t]     = __floats2bfloat162_rn(a.x * scale, a.y * scale);
    o2[2 * t + 1] = __floats2bfloat162_rn(a.z * scale, a.w * scale);
}

// ---------------- Kernel 2: persistent fused triangular GEMM + dual argmax ----------------
extern __shared__ __align__(128) char smem_dyn[];

__global__ __launch_bounds__(256) void nn_gemm_kernel() {
    __shared__ unsigned long long sred[BM];
    __shared__ unsigned long long scol[BN];

    const int tid = threadIdx.x;
    const int lane = tid & 31;
    const int warpId = tid >> 5;

    const uint32_t smA = smem_u32(smem_dyn);
    const uint32_t smB = smA + STAGES * A_STAGE;

    // ---- per-thread ldmatrix address components ----
    const int wM = warpId & 1, wN = warpId >> 1;      // 2 x 4 warps
    const int wrb = wM * 64, wcb = wN * 64;           // warp tile 64x64
    const int arow = wrb + (lane & 7) + ((lane >> 3) & 1) * 8;
    const int achk = lane >> 4;                       // 0/1 (16B chunk within k16)
    const int asw  = arow & 7;
    const int brow = wcb + (lane & 7) + ((lane >> 4) & 1) * 8;
    const int bchk = (lane >> 3) & 1;
    const int bsw  = brow & 7;

    // cp.async mapping: A 2048 16B-chunks/stage (8/thread), B 4096 (16/thread)
    const int cpr  = tid >> 4;           // base row (stride 16 rows)
    const int cpc  = tid & 15;           // chunk col 0..15

    int tId = blockIdx.x;
    if (tId >= NTILES) return;
    int rowBase, colBase;
    decode_tile(tId, rowBase, colBase);

    // ---- first tile prologue: stage 0 -> slot 0 ----
    {
        const __nv_bfloat16* gA = g_xn + (size_t)rowBase * DIM;
        const __nv_bfloat16* gB = g_xn + (size_t)colBase * DIM;
        #pragma unroll
        for (int i = 0; i < 8; i++) {
            const int r = cpr + i * 16;
            cp16(smA + r * 256 + ((cpc ^ (r & 7)) << 4), gA + (size_t)r * DIM + cpc * 8);
        }
        #pragma unroll
        for (int i = 0; i < 16; i++) {
            const int r = cpr + i * 16;
            cp16(smB + r * 256 + ((cpc ^ (r & 7)) << 4), gB + (size_t)r * DIM + cpc * 8);
        }
        CP_COMMIT();
    }

    while (true) {
        const bool isDiag = (rowBase >= colBase);
        const int nextId = tId + GRID_P;
        const bool hasNext = (nextId < NTILES);
        int nRowBase = 0, nColBase = 0;
        if (hasNext) decode_tile(nextId, nRowBase, nColBase);

        const __nv_bfloat16* gA = g_xn + (size_t)rowBase * DIM;
        const __nv_bfloat16* gB = g_xn + (size_t)colBase * DIM;

        if (tid < BM) sred[tid] = 0ull;
        scol[tid] = 0ull;

        float acc[4][8][4];
        #pragma unroll
        for (int i = 0; i < 4; i++)
            #pragma unroll
            for (int j = 0; j < 8; j++)
                #pragma unroll
                for (int k = 0; k < 4; k++) acc[i][j][k] = 0.f;

        for (int kt = 0; kt < NK; kt++) {
            CP_WAIT0();
            __syncthreads();

            const int cur = kt & 1;
            const int nxt = cur ^ 1;
            const uint32_t Ab = smA + cur * A_STAGE;
            const uint32_t Bb = smB + cur * B_STAGE;

            // unified prefetch source (next k-stage of this tile, or next tile's stage 0)
            const __nv_bfloat16* srcA;
            const __nv_bfloat16* srcB;
            bool doLoad = true;
            if (kt + 1 < NK) {
                srcA = gA + (kt + 1) * BK;
                srcB = gB + (kt + 1) * BK;
            } else if (hasNext) {
                srcA = g_xn + (size_t)nRowBase * DIM;
                srcB = g_xn + (size_t)nColBase * DIM;
            } else {
                srcA = nullptr; srcB = nullptr; doLoad = false;
            }

            // ---- 8 k16 chunks; cp.async spread across chunks 0..2 ----
            uint32_t ra[4][4], rb[8][2];
            #pragma unroll
            for (int kk = 0; kk < 8; kk++) {
                #pragma unroll
                for (int mt = 0; mt < 4; mt++) {
                    const uint32_t a = Ab + (arow + mt * 16) * 256 + (((kk * 2 + achk) ^ asw) << 4);
                    LDSM_X4(ra[mt][0], ra[mt][1], ra[mt][2], ra[mt][3], a);
                }
                #pragma unroll
                for (int p = 0; p < 4; p++) {
                    const uint32_t b = Bb + (brow + p * 16) * 256 + (((kk * 2 + bchk) ^ bsw) << 4);
                    LDSM_X4(rb[2 * p][0], rb[2 * p][1], rb[2 * p + 1][0], rb[2 * p + 1][1], b);
                }
                #pragma unroll
                for (int mt = 0; mt < 4; mt++)
                    #pragma unroll
                    for (int nt = 0; nt < 8; nt++)
                        mma16816(acc[mt][nt], ra[mt], rb[nt]);

                // spread the 24-inst cp.async burst across chunk boundaries
                if (kk == 0 && doLoad) {
                    #pragma unroll
                    for (int i = 0; i < 8; i++) {
                        const int r = cpr + i * 16;
                        cp16(smA + nxt * A_STAGE + r * 256 + ((cpc ^ (r & 7)) << 4),
                             srcA + (size_t)r * DIM + cpc * 8);
                    }
                } else if (kk == 1 && doLoad) {
                    #pragma unroll
                    for (int i = 0; i < 8; i++) {
                        const int r = cpr + i * 16;
                        cp16(smB + nxt * B_STAGE + r * 256 + ((cpc ^ (r & 7)) << 4),
                             srcB + (size_t)r * DIM + cpc * 8);
                    }
                } else if (kk == 2) {
                    if (doLoad) {
                        #pragma unroll
                        for (int i = 8; i < 16; i++) {
                            const int r = cpr + i * 16;
                            cp16(smB + nxt * B_STAGE + r * 256 + ((cpc ^ (r & 7)) << 4),
                                 srcB + (size_t)r * DIM + cpc * 8);
                        }
                    }
                    CP_COMMIT();
                }
            }
        }

        const int g = lane >> 2, t4 = lane & 3;

        // ---- epilogue A: per-row argmax over this tile's 256 columns, diag masked ----
        #pragma unroll
        for (int mt = 0; mt < 4; mt++) {
            const int r0 = rowBase + wrb + mt * 16 + g;
            const int r1 = r0 + 8;
            float m0 = -10.f, m1 = -10.f;
            int j0 = 0, j1 = 0;
            #pragma unroll
            for (int nt = 0; nt < 8; nt++) {
                const int c = colBase + wcb + nt * 8 + 2 * t4;
                float v;
                v = acc[mt][nt][0]; if (c     != r0 && v > m0) { m0 = v; j0 = c;     }
                v = acc[mt][nt][1]; if (c + 1 != r0 && v > m0) { m0 = v; j0 = c + 1; }
                v = acc[mt][nt][2]; if (c     != r1 && v > m1) { m1 = v; j1 = c;     }
                v = acc[mt][nt][3]; if (c + 1 != r1 && v > m1) { m1 = v; j1 = c + 1; }
            }
            unsigned long long p0 = ((unsigned long long)f2ord(m0) << 32) | (unsigned)j0;
            unsigned long long p1 = ((unsigned long long)f2ord(m1) << 32) | (unsigned)j1;
            #pragma unroll
            for (int off = 1; off < 4; off <<= 1) {
                unsigned long long q0 = __shfl_xor_sync(0xffffffffu, p0, off);
                unsigned long long q1 = __shfl_xor_sync(0xffffffffu, p1, off);
                if (q0 > p0) p0 = q0;
                if (q1 > p1) p1 = q1;
            }
            if (t4 == 0) {
                atomicMax(&sred[wrb + mt * 16 + g], p0);
                atomicMax(&sred[wrb + mt * 16 + g + 8], p1);
            }
        }

        // ---- epilogue B: per-column argmax (symmetry), off-diag tiles only ----
        if (!isDiag) {
            #pragma unroll
            for (int nt = 0; nt < 8; nt++) {
                const int cl = wcb + nt * 8 + 2 * t4;
                float ce = -10.f, co = -10.f;
                int re = 0, ro = 0;
                #pragma unroll
                for (int mt = 0; mt < 4; mt++) {
                    const int r0 = rowBase + wrb + mt * 16 + g;
                    const int r1 = r0 + 8;
                    float v;
                    v = acc[mt][nt][0]; if (v > ce) { ce = v; re = r0; }
                    v = acc[mt][nt][2]; if (v > ce) { ce = v; re = r1; }
                    v = acc[mt][nt][1]; if (v > co) { co = v; ro = r0; }
                    v = acc[mt][nt][3]; if (v > co) { co = v; ro = r1; }
                }
                unsigned long long pe = ((unsigned long long)f2ord(ce) << 32) | (unsigned)re;
                unsigned long long po = ((unsigned long long)f2ord(co) << 32) | (unsigned)ro;
                #pragma unroll
                for (int off = 4; off < 32; off <<= 1) {
                    unsigned long long qe = __shfl_xor_sync(0xffffffffu, pe, off);
                    unsigned long long qo = __shfl_xor_sync(0xffffffffu, po, off);
                    if (qe > pe) pe = qe;
                    if (qo > po) po = qo;
                }
                if (g == 0) {
                    atomicMax(&scol[cl], pe);
                    atomicMax(&scol[cl + 1], po);
                }
            }
        }

        __syncthreads();
        if (tid < BM) atomicMax(&g_best[rowBase + tid], sred[tid]);
        if (!isDiag) atomicMax(&g_best[colBase + tid], scol[tid]);
        __syncthreads();   // protect sred/scol from next tile's re-zeroing

        if (!hasNext) break;
        tId = nextId;
        rowBase = nRowBase;
        colBase = nColBase;
    }
}

// ---------------- Kernel 3: distances + -log(d) + fused deterministic reduction ----------------
__global__ void loss_kernel(const float* __restrict__ x, float* __restrict__ out) {
    const int gw = (blockIdx.x * blockDim.x + threadIdx.x) >> 5;  // 4096 warps
    const int lane = threadIdx.x & 31;
    float accum = 0.f;
    for (int row = gw; row < NROWS; row += 4096) {
        const int j = (int)(g_best[row] & 0xffffffffu);
        const float4* a = (const float4*)(x + (size_t)row * DIM);
        const float4* b = (const float4*)(x + (size_t)j * DIM);
        float s = 0.f;
        #pragma unroll 4
        for (int i = lane; i < DIM / 4; i += 32) {
            float4 va = a[i], vb = b[i];
            float d0 = va.x - vb.x + 1e-6f;
            float d1 = va.y - vb.y + 1e-6f;
            float d2 = va.z - vb.z + 1e-6f;
            float d3 = va.w - vb.w + 1e-6f;
            s += d0 * d0 + d1 * d1 + d2 * d2 + d3 * d3;
        }
        #pragma unroll
        for (int off = 16; off > 0; off >>= 1) s += __shfl_xor_sync(0xffffffffu, s, off);
        if (lane == 0) accum += -0.5f * logf(s);   // -log(sqrt(s))
    }
    if (lane == 0) g_partial[gw] = accum;

    // ---- last-block-done final reduction (deterministic: fixed summation order) ----
    __shared__ bool isLast;
    __threadfence();
    __syncthreads();
    if (threadIdx.x == 0) {
        int c = atomicAdd(&g_count, 1);
        isLast = (c == LOSS_BLOCKS - 1);
    }
    __syncthreads();
    if (isLast) {
        __shared__ float red[256];
        const int t = threadIdx.x;
        float s = 0.f;
        for (int i = t; i < 4096; i += 256) s += g_partial[i];
        red[t] = s;
        __syncthreads();
        for (int o = 128; o > 0; o >>= 1) {
            if (t < o) red[t] += red[t + o];
            __syncthreads();
        }
        if (t == 0) out[0] = red[0] * (1.0f / NROWS);
    }
}

extern "C" void kernel_launch(void* const* d_in, const int* in_sizes, int n_in,
                              void* d_out, int out_size) {
    (void)in_sizes; (void)n_in; (void)out_size;
    const float* x = (const float*)d_in[0];
    float* out = (float*)d_out;

    cudaFuncSetAttribute(nn_gemm_kernel, cudaFuncAttributeMaxDynamicSharedMemorySize, SMEM_DYN);

    prep_kernel<<<NROWS, 256>>>(x);
    nn_gemm_kernel<<<GRID_P, 256, SMEM_DYN>>>();
    loss_kernel<<<LOSS_BLOCKS, 256>>>(x, out);
}